// round 8
// baseline (speedup 1.0000x reference)
#include <cuda_runtime.h>
#include <math.h>

// ---------------- problem constants ----------------
#define Bs      8
#define HEAD    512
#define FMP     40
#define NPOS    1600      // FMP*FMP
#define NCLS    20
#define CONF_T  0.001f
#define NMS_T   0.6f

// output layout (float32): bboxes | best | cls_inds | keep
#define OFF_BEST  (Bs*NPOS*4)          // 51200
#define OFF_CLS   (OFF_BEST + Bs*NPOS) // 64000
#define OFF_KEEP  (OFF_CLS  + Bs*NPOS) // 76800

#define WPER (512L*4608L)              // floats per conv layer (512 oc x 512 ic x 9)
#define OCGW (128L*36L*128L)           // floats per (layer, ocg) in wT = 589824
#define ACT_N (Bs * HEAD * NPOS)       // 6,553,600 activations

// ---------------- scratch (device globals, no runtime alloc) ----------------
__device__ float g_bufA[ACT_N];
__device__ float g_bufB[ACT_N];
__device__ float g_bufC[ACT_N];
__device__ float g_p0[ACT_N];          // split-K partial (k-half 0)
__device__ float g_p1[ACT_N];          // split-K partial (k-half 1)
__device__ float g_best[Bs * NPOS];
__device__ int   g_clsi[Bs * NPOS];
__device__ float g_wT[6 * WPER];       // transposed weights, 56.6 MB

// ---------------- packed f32x2 / cp.async helpers ----------------
__device__ __forceinline__ void fma2(float2 &d, float2 a, float2 b) {
    asm("fma.rn.f32x2 %0, %1, %2, %0;"
        : "+l"(reinterpret_cast<unsigned long long&>(d))
        : "l"(reinterpret_cast<unsigned long long&>(a)),
          "l"(reinterpret_cast<unsigned long long&>(b)));
}
__device__ __forceinline__ void cp_async16(unsigned smem_addr, const void* gptr) {
    asm volatile("cp.async.cg.shared.global [%0], [%1], 16;"
                 :: "r"(smem_addr), "l"(gptr));
}
__device__ __forceinline__ void cp_commit()  { asm volatile("cp.async.commit_group;"); }
__device__ __forceinline__ void cp_wait0()   { asm volatile("cp.async.wait_group 0;" ::: "memory"); }

// ---------------- weight pre-transform ----------------
// dst layout per layer: [ocg(4)][s(128)][kk(36)][oc_in(128)]  (s = ic-group of 4)
// src layout: [oc(512)][ic(512)][3][3]
__global__ void __launch_bounds__(256)
wtransform_k(const float* __restrict__ cls_w, const float* __restrict__ reg_w,
             float* __restrict__ wT)
{
    long i = (long)blockIdx.x * 256 + threadIdx.x;
    if (i >= 6 * WPER) return;
    int  l  = (int)(i / WPER);
    long r  = i - (long)l * WPER;
    int  oc_in = (int)(r & 127);
    long t  = r >> 7;             // ((ocg*128+s)*36 + kk)
    int  kk = (int)(t % 36);
    long u  = t / 36;
    int  s  = (int)(u & 127);
    int  ocg = (int)(u >> 7);
    int  ic  = s * 4 + kk / 9;
    int  k9  = kk % 9;
    const float* src = (l < 2) ? (cls_w + (long)l * WPER)
                               : (reg_w + (long)(l - 2) * WPER);
    wT[i] = src[(long)(ocg * 128 + oc_in) * 4608 + (long)ic * 9 + k9];
}

// ---------------- conv 3x3 partial (no bias/act), 2 y-rows, split-K ----------------
// grid: (20 y-pairs, 8 = ocg*? : y-dim packs [ocg(4) | khalf(2)], 8 batch), block 128
// thread: og = tid>>2 -> oc (og*4 .. og*4+3) as 2 f32x2 pairs; xs = tid&3 -> x0 = xs*10
// Each thread accumulates 2 y-rows: input rows y0-1..y0+2 are shared across both.
__global__ void __launch_bounds__(128, 4)
conv3x3_part_k(const float* __restrict__ in, const float* __restrict__ wT,
               float* __restrict__ p0, float* __restrict__ p1)
{
    __shared__ float  s_wbuf[2][36 * 128];     // 2 x 18432 B
    __shared__ float2 s_ibuf[2][4 * 4 * 42];   // 2 x 5376 B (4 ic x 4 rows x 42, dup pairs)

    const int y0    = blockIdx.x * 2;
    const int ocg   = blockIdx.y & 3;
    const int kh    = blockIdx.y >> 2;
    const int b     = blockIdx.z;
    const int tid   = threadIdx.x;
    const int og    = tid >> 2;
    const int xs    = tid & 3;
    const int x0    = xs * 10;
    const int sbase = kh * 64;

    float2 acc[2][2][10];                      // [oc-pair j][dy][x]
#pragma unroll
    for (int j = 0; j < 2; j++)
#pragma unroll
        for (int dy = 0; dy < 2; dy++)
#pragma unroll
            for (int x = 0; x < 10; x++) acc[j][dy][x] = make_float2(0.f, 0.f);

    const float* inb   = in + (long)b * HEAD * NPOS;
    const float* wbase = wT + (long)ocg * OCGW + (long)sbase * (36 * 128);

    // ---- input prefetch (672 elems = 4 ic x 4 rows x 42, 6 per thread) ----
    auto load_in = [&](int s, float* rv) {
#pragma unroll
        for (int k = 0; k < 6; k++) {
            int idx = tid + 128 * k;
            float v = 0.f;
            if (idx < 672) {
                int ic = idx / 168;
                int r2 = idx - ic * 168;
                int r  = r2 / 42;
                int xx = r2 - r * 42;
                int yy = y0 + r - 1;
                int xg = xx - 1;
                if ((unsigned)yy < (unsigned)FMP && (unsigned)xg < (unsigned)FMP)
                    v = inb[((sbase + s) * 4 + ic) * NPOS + yy * FMP + xg];
            }
            rv[k] = v;
        }
    };
    auto store_in = [&](int buf, const float* rv) {
#pragma unroll
        for (int k = 0; k < 6; k++) {
            int idx = tid + 128 * k;
            if (idx < 672)
                s_ibuf[buf][idx] = make_float2(rv[k], rv[k]);
        }
    };
    // ---- weight stage: 1152 float4, 9 per thread, via cp.async ----
    auto stage_w = [&](int buf, int s) {
        unsigned wdst = (unsigned)__cvta_generic_to_shared(&s_wbuf[buf][0]) + tid * 16;
        const float4* wsrc = (const float4*)(wbase + (long)s * 36 * 128) + tid;
#pragma unroll
        for (int k = 0; k < 9; k++)
            cp_async16(wdst + 128 * 16 * k, wsrc + 128 * k);
    };

    // ---- prologue ----
    {
        float rv[6];
        stage_w(0, 0);
        cp_commit();
        load_in(0, rv);
        store_in(0, rv);
        cp_wait0();
    }
    __syncthreads();

    for (int s = 0; s < 64; s++) {
        const int cur = s & 1;
        float rv[6];
        if (s < 63) {
            stage_w(1 - cur, s + 1);
            cp_commit();
            load_in(s + 1, rv);
        }

        const float*  s_w   = s_wbuf[cur];
        const float2* s_in2 = s_ibuf[cur];

#pragma unroll 1
        for (int ic = 0; ic < 4; ic++) {
#pragma unroll
            for (int r = 0; r < 4; r++) {
                // one staged row feeds output y0 (ky=r) and y0+1 (ky=r-1)
                const float4* sr4 =
                    (const float4*)(s_in2 + (ic * 4 + r) * 42 + x0);
                float2 iv[12];
#pragma unroll
                for (int i = 0; i < 6; i++) {
                    float4 q = sr4[i];
                    iv[2 * i]     = make_float2(q.x, q.y);
                    iv[2 * i + 1] = make_float2(q.z, q.w);
                }
                if (r < 3) {    // y0 output, ky = r
                    const float4* wrow4 =
                        (const float4*)(s_w + (ic * 9 + r * 3) * 128) + og;
#pragma unroll
                    for (int kx = 0; kx < 3; kx++) {
                        float4 wq = wrow4[kx * 32];
                        float2 w0 = make_float2(wq.x, wq.y);
                        float2 w1 = make_float2(wq.z, wq.w);
#pragma unroll
                        for (int x = 0; x < 10; x++) {
                            fma2(acc[0][0][x], w0, iv[x + kx]);
                            fma2(acc[1][0][x], w1, iv[x + kx]);
                        }
                    }
                }
                if (r >= 1) {   // y0+1 output, ky = r-1
                    const float4* wrow4 =
                        (const float4*)(s_w + (ic * 9 + (r - 1) * 3) * 128) + og;
#pragma unroll
                    for (int kx = 0; kx < 3; kx++) {
                        float4 wq = wrow4[kx * 32];
                        float2 w0 = make_float2(wq.x, wq.y);
                        float2 w1 = make_float2(wq.z, wq.w);
#pragma unroll
                        for (int x = 0; x < 10; x++) {
                            fma2(acc[0][1][x], w0, iv[x + kx]);
                            fma2(acc[1][1][x], w1, iv[x + kx]);
                        }
                    }
                }
            }
        }

        if (s < 63) {
            store_in(1 - cur, rv);
            cp_wait0();
        }
        __syncthreads();
    }

    float* po = kh ? p1 : p0;
#pragma unroll
    for (int j2 = 0; j2 < 2; j2++) {
        int oc0 = ocg * 128 + og * 4 + j2 * 2;
#pragma unroll
        for (int dy = 0; dy < 2; dy++) {
            float* o0 = po + ((long)b * HEAD + oc0) * NPOS + (y0 + dy) * FMP + x0;
            float* o1 = o0 + NPOS;
#pragma unroll
            for (int x = 0; x < 10; x++) {
                o0[x] = acc[j2][dy][x].x;
                o1[x] = acc[j2][dy][x].y;
            }
        }
    }
}

// ---------------- combine partials + bias + leaky ----------------
__global__ void __launch_bounds__(256)
combine_k(const float4* __restrict__ p0, const float4* __restrict__ p1,
          const float* __restrict__ bias, float4* __restrict__ out)
{
    int i = blockIdx.x * 256 + threadIdx.x;
    if (i >= ACT_N / 4) return;
    int oc = (i / (NPOS / 4)) & (HEAD - 1);
    float bv = bias[oc];
    float4 a = p0[i], c = p1[i];
    float4 r;
    float v;
    v = a.x + c.x + bv; r.x = v > 0.f ? v : 0.1f * v;
    v = a.y + c.y + bv; r.y = v > 0.f ? v : 0.1f * v;
    v = a.z + c.z + bv; r.z = v > 0.f ? v : 0.1f * v;
    v = a.w + c.w + bv; r.w = v > 0.f ? v : 0.1f * v;
    out[i] = r;
}

// ---------------- 1x1 heads + decode (boxes, best, argmax, keep init) ----------------
__global__ void __launch_bounds__(160)
heads_decode_k(const float* __restrict__ cf, const float* __restrict__ rf,
               const float* __restrict__ obj_w, const float* __restrict__ obj_b,
               const float* __restrict__ clsp_w, const float* __restrict__ clsp_b,
               const float* __restrict__ regp_w, const float* __restrict__ regp_b,
               float* __restrict__ out, float* __restrict__ best_s, int* __restrict__ cls_s)
{
    const int b = blockIdx.y;
    const int n = blockIdx.x * 160 + threadIdx.x;

    const float* cfb = cf + (long)b * HEAD * NPOS + n;
    const float* rfb = rf + (long)b * HEAD * NPOS + n;

    float accC[NCLS];
    float accR[4];
    float accO = 0.f;
#pragma unroll
    for (int c = 0; c < NCLS; c++) accC[c] = 0.f;
#pragma unroll
    for (int k = 0; k < 4; k++) accR[k] = 0.f;

#pragma unroll 4
    for (int ch = 0; ch < HEAD; ch++) {
        float cv = cfb[(long)ch * NPOS];
        float rv = rfb[(long)ch * NPOS];
        accO = fmaf(rv, __ldg(&obj_w[ch]), accO);
#pragma unroll
        for (int k = 0; k < 4; k++)
            accR[k] = fmaf(rv, __ldg(&regp_w[k * HEAD + ch]), accR[k]);
#pragma unroll
        for (int c = 0; c < NCLS; c++)
            accC[c] = fmaf(cv, __ldg(&clsp_w[c * HEAD + ch]), accC[c]);
    }

    accO += obj_b[0];
#pragma unroll
    for (int k = 0; k < 4; k++) accR[k] += regp_b[k];
#pragma unroll
    for (int c = 0; c < NCLS; c++) accC[c] += clsp_b[c];

    float m = accC[0];
    int am = 0;
#pragma unroll
    for (int c = 1; c < NCLS; c++)
        if (accC[c] > m) { m = accC[c]; am = c; }
    float s = 0.f;
#pragma unroll
    for (int c = 0; c < NCLS; c++) s += expf(accC[c] - m);
    float sig_o = 1.f / (1.f + expf(-accO));
    float best  = sig_o / s;

    float gx = (float)(n % FMP);
    float gy = (float)(n / FMP);
    float cx = 1.f / (1.f + expf(-accR[0])) + gx;
    float cy = 1.f / (1.f + expf(-accR[1])) + gy;
    float ww = expf(accR[2]);
    float hh = expf(accR[3]);

    float bx1 = (cx - ww * 0.5f) * 32.f / 1280.f;
    float by1 = (cy - hh * 0.5f) * 32.f / 1280.f;
    float bx2 = (cx + ww * 0.5f) * 32.f / 1280.f;
    float by2 = (cy + hh * 0.5f) * 32.f / 1280.f;
    bx1 = fminf(fmaxf(bx1, 0.f), 1.f);
    by1 = fminf(fmaxf(by1, 0.f), 1.f);
    bx2 = fminf(fmaxf(bx2, 0.f), 1.f);
    by2 = fminf(fmaxf(by2, 0.f), 1.f);

    const int gi = b * NPOS + n;
    out[gi * 4 + 0] = bx1;
    out[gi * 4 + 1] = by1;
    out[gi * 4 + 2] = bx2;
    out[gi * 4 + 3] = by2;
    out[OFF_BEST + gi] = best;
    out[OFF_CLS  + gi] = (float)am;
    out[OFF_KEEP + gi] = 0.f;
    best_s[gi] = best;
    cls_s[gi]  = am;
}

// ---------------- per-(batch, class) greedy NMS ----------------
__global__ void __launch_bounds__(256)
nms_k(const float* __restrict__ out_boxes,
      float* __restrict__ out_keep,
      const float* __restrict__ best_s, const int* __restrict__ cls_s)
{
    const int b = blockIdx.x / NCLS;
    const int c = blockIdx.x % NCLS;
    const int tid = threadIdx.x;

    __shared__ float sx1[NPOS], sy1[NPOS], sx2[NPOS], sy2[NPOS];
    __shared__ float ssc[NPOS];
    __shared__ int   sidx[NPOS];
    __shared__ unsigned short ord[NPOS];
    __shared__ unsigned char aliveR[NPOS];
    __shared__ int scnt;

    if (tid == 0) scnt = 0;
    __syncthreads();

    for (int n = tid; n < NPOS; n += 256) {
        int gi = b * NPOS + n;
        if (cls_s[gi] == c && best_s[gi] >= CONF_T) {
            int p = atomicAdd(&scnt, 1);
            sidx[p] = n;
            ssc[p]  = best_s[gi];
            const float* bp = out_boxes + (long)gi * 4;
            sx1[p] = bp[0]; sy1[p] = bp[1]; sx2[p] = bp[2]; sy2[p] = bp[3];
        }
    }
    __syncthreads();
    const int cnt = scnt;

    for (int i = tid; i < cnt; i += 256) {
        float si = ssc[i];
        int   ii = sidx[i];
        int rnk = 0;
        for (int j = 0; j < cnt; j++) {
            float sj = ssc[j];
            if (sj > si || (sj == si && sidx[j] < ii)) rnk++;
        }
        ord[rnk] = (unsigned short)i;
        aliveR[rnk] = 1;
    }
    __syncthreads();

    for (int r = 0; r < cnt; r++) {
        __syncthreads();
        if (!aliveR[r]) continue;
        int li = ord[r];
        float bx1 = sx1[li], by1 = sy1[li], bx2 = sx2[li], by2 = sy2[li];
        float ai = (bx2 - bx1) * (by2 - by1);
        for (int rr = r + 1 + tid; rr < cnt; rr += 256) {
            if (!aliveR[rr]) continue;
            int lj = ord[rr];
            float jx1 = sx1[lj], jy1 = sy1[lj], jx2 = sx2[lj], jy2 = sy2[lj];
            float xx1 = fmaxf(bx1, jx1);
            float yy1 = fmaxf(by1, jy1);
            float xx2 = fminf(bx2, jx2);
            float yy2 = fminf(by2, jy2);
            float w2 = fmaxf(1e-28f, xx2 - xx1);
            float h2 = fmaxf(1e-28f, yy2 - yy1);
            float inter = w2 * h2;
            float aj = (jx2 - jx1) * (jy2 - jy1);
            float iou = inter / (ai + aj - inter + 1e-14f);
            if (iou > NMS_T) aliveR[rr] = 0;
        }
    }
    __syncthreads();

    for (int r = tid; r < cnt; r += 256)
        if (aliveR[r])
            out_keep[b * NPOS + sidx[ord[r]]] = 1.f;
}

// ---------------- launch ----------------
extern "C" void kernel_launch(void* const* d_in, const int* in_sizes, int n_in,
                              void* d_out, int out_size)
{
    const float* x      = (const float*)d_in[0];
    const float* cls_w  = (const float*)d_in[1];
    const float* cls_b  = (const float*)d_in[2];
    const float* reg_w  = (const float*)d_in[3];
    const float* reg_b  = (const float*)d_in[4];
    const float* obj_w  = (const float*)d_in[5];
    const float* obj_b  = (const float*)d_in[6];
    const float* clsp_w = (const float*)d_in[7];
    const float* clsp_b = (const float*)d_in[8];
    const float* regp_w = (const float*)d_in[9];
    const float* regp_b = (const float*)d_in[10];
    float* out = (float*)d_out;

    void *pA, *pB, *pC, *pP0, *pP1, *pBest, *pCls, *pWT;
    cudaGetSymbolAddress(&pA, g_bufA);
    cudaGetSymbolAddress(&pB, g_bufB);
    cudaGetSymbolAddress(&pC, g_bufC);
    cudaGetSymbolAddress(&pP0, g_p0);
    cudaGetSymbolAddress(&pP1, g_p1);
    cudaGetSymbolAddress(&pBest, g_best);
    cudaGetSymbolAddress(&pCls, g_clsi);
    cudaGetSymbolAddress(&pWT, g_wT);
    float* bufA = (float*)pA;
    float* bufB = (float*)pB;
    float* bufC = (float*)pC;
    float* part0 = (float*)pP0;
    float* part1 = (float*)pP1;
    float* bestp = (float*)pBest;
    int*   clsp  = (int*)pCls;
    float* wT    = (float*)pWT;

    // one-shot weight transform (deterministic, graph-capturable)
    {
        long total = 6 * WPER;
        int  grid  = (int)((total + 255) / 256);
        wtransform_k<<<grid, 256>>>(cls_w, reg_w, wT);
    }

    dim3 cgrid(FMP / 2, 8, Bs);     // (y-pairs, ocg*khalf, batch) = 1280 blocks
    dim3 cblk(128);
    const int ngrid = (ACT_N / 4 + 255) / 256;

    auto conv = [&](const float* src, const float* w, const float* bias_p, float* dst) {
        conv3x3_part_k<<<cgrid, cblk>>>(src, w, part0, part1);
        combine_k<<<ngrid, 256>>>((const float4*)part0, (const float4*)part1,
                                  bias_p, (float4*)dst);
    };

    // cls branch: x -> bufA -> bufB   (cf = bufB)
    conv(x,    wT + 0 * WPER, cls_b,        bufA);
    conv(bufA, wT + 1 * WPER, cls_b + HEAD, bufB);
    // reg branch: x -> bufA -> bufC -> bufA -> bufC   (rf = bufC)
    conv(x,    wT + 2 * WPER, reg_b,            bufA);
    conv(bufA, wT + 3 * WPER, reg_b + HEAD,     bufC);
    conv(bufC, wT + 4 * WPER, reg_b + 2 * HEAD, bufA);
    conv(bufA, wT + 5 * WPER, reg_b + 3 * HEAD, bufC);

    heads_decode_k<<<dim3(10, Bs), 160>>>(bufB, bufC,
                                          obj_w, obj_b, clsp_w, clsp_b,
                                          regp_w, regp_b,
                                          out, bestp, clsp);

    nms_k<<<Bs * NCLS, 256>>>(out, out + OFF_KEEP, bestp, clsp);
}

// round 9
// speedup vs baseline: 1.1372x; 1.1372x over previous
#include <cuda_runtime.h>
#include <math.h>

// ---------------- problem constants ----------------
#define Bs      8
#define HEAD    512
#define FMP     40
#define NPOS    1600      // FMP*FMP
#define NCLS    20
#define CONF_T  0.001f
#define NMS_T   0.6f

// output layout (float32): bboxes | best | cls_inds | keep
#define OFF_BEST  (Bs*NPOS*4)          // 51200
#define OFF_CLS   (OFF_BEST + Bs*NPOS) // 64000
#define OFF_KEEP  (OFF_CLS  + Bs*NPOS) // 76800

#define WPER (512L*4608L)              // floats per conv layer (512 oc x 512 ic x 9)
#define OCGW (256L*18L*128L)           // floats per (layer, ocg) in wT = 589824
#define ACT_N (Bs * HEAD * NPOS)       // 6,553,600 activations

// ---------------- scratch (device globals, no runtime alloc) ----------------
__device__ float g_bufA[ACT_N];
__device__ float g_bufB[ACT_N];
__device__ float g_bufC[ACT_N];
__device__ float g_bufD[ACT_N];        // cls-chain intermediate (parallel stream)
__device__ float g_best[Bs * NPOS];
__device__ int   g_clsi[Bs * NPOS];
__device__ float g_wT[6 * WPER];       // transposed weights, 56.6 MB

// ---------------- packed f32x2 / cp.async helpers ----------------
__device__ __forceinline__ void fma2(float2 &d, float2 a, float2 b) {
    asm("fma.rn.f32x2 %0, %1, %2, %0;"
        : "+l"(reinterpret_cast<unsigned long long&>(d))
        : "l"(reinterpret_cast<unsigned long long&>(a)),
          "l"(reinterpret_cast<unsigned long long&>(b)));
}
__device__ __forceinline__ void cp_async16(unsigned smem_addr, const void* gptr) {
    asm volatile("cp.async.cg.shared.global [%0], [%1], 16;"
                 :: "r"(smem_addr), "l"(gptr));
}
__device__ __forceinline__ void cp_commit()  { asm volatile("cp.async.commit_group;"); }
__device__ __forceinline__ void cp_wait0()   { asm volatile("cp.async.wait_group 0;" ::: "memory"); }

// ---------------- weight pre-transform ----------------
// dst layout per layer: [ocg(4)][s(256)][kk(18)][oc_in(128)]  (s = ic-pair)
// src layout: [oc(512)][ic(512)][3][3]
__global__ void __launch_bounds__(256)
wtransform_k(const float* __restrict__ cls_w, const float* __restrict__ reg_w,
             float* __restrict__ wT)
{
    long i = (long)blockIdx.x * 256 + threadIdx.x;
    if (i >= 6 * WPER) return;
    int  l  = (int)(i / WPER);
    long r  = i - (long)l * WPER;
    int  oc_in = (int)(r & 127);
    long t  = r >> 7;             // ((ocg*256+s)*18 + kk)
    int  kk = (int)(t % 18);
    long u  = t / 18;
    int  s  = (int)(u & 255);
    int  ocg = (int)(u >> 8);
    int  ic  = s * 2 + kk / 9;
    int  k9  = kk % 9;
    const float* src = (l < 2) ? (cls_w + (long)l * WPER)
                               : (reg_w + (long)(l - 2) * WPER);
    wT[i] = src[(long)(ocg * 128 + oc_in) * 4608 + (long)ic * 9 + k9];
}

// ---------------- conv 3x3 (pad 1) + bias + leaky ----------------
// f32x2 packed, ic-step 2, cp.async double-buffered weights + reg-prefetched input.
// grid: (40 y-rows, 4 oc-groups of 128, 8 batch), block: 128 threads
// thread: og = tid>>2 -> oc pairs (og*4, og*4+1), (og*4+2, og*4+3); xs = tid&3 -> x0 = xs*10
__global__ void __launch_bounds__(128, 5)
conv3x3_leaky_k(const float* __restrict__ in, const float* __restrict__ wT,
                const float* __restrict__ bias, float* __restrict__ out)
{
    __shared__ float  s_wbuf[2][18 * 128];     // 2 x 9216 B
    __shared__ float2 s_ibuf[2][2 * 3 * 42];   // 2 x 2016 B (duplicated input pairs)

    const int y   = blockIdx.x;
    const int ocg = blockIdx.y;
    const int b   = blockIdx.z;
    const int tid = threadIdx.x;
    const int og  = tid >> 2;
    const int xs  = tid & 3;
    const int x0  = xs * 10;

    float2 acc[2][10];
#pragma unroll
    for (int j = 0; j < 2; j++)
#pragma unroll
        for (int x = 0; x < 10; x++) acc[j][x] = make_float2(0.f, 0.f);

    const float* inb   = in + (long)b * HEAD * NPOS;
    const float* wbase = wT + (long)ocg * OCGW;

    // ---- input prefetch helpers (252 elems, 2 per thread) ----
    auto load_in = [&](int s, float* rv) {
#pragma unroll
        for (int k = 0; k < 2; k++) {
            int idx = tid + 128 * k;
            float v = 0.f;
            if (idx < 252) {
                int ic = idx / 126;
                int r2 = idx - ic * 126;
                int ky = r2 / 42;
                int xx = r2 - ky * 42;
                int yy = y + ky - 1;
                int xg = xx - 1;
                if ((unsigned)yy < (unsigned)FMP && (unsigned)xg < (unsigned)FMP)
                    v = inb[(s * 2 + ic) * NPOS + yy * FMP + xg];
            }
            rv[k] = v;
        }
    };
    auto store_in = [&](int buf, const float* rv) {
#pragma unroll
        for (int k = 0; k < 2; k++) {
            int idx = tid + 128 * k;
            if (idx < 252)
                s_ibuf[buf][idx] = make_float2(rv[k], rv[k]);
        }
    };
    // ---- weight stage: 576 float4 per step, via cp.async ----
    auto stage_w = [&](int buf, int s) {
        unsigned wdst = (unsigned)__cvta_generic_to_shared(&s_wbuf[buf][0]);
        const float4* wsrc = (const float4*)(wbase + (long)s * 18 * 128);
#pragma unroll
        for (int k = 0; k < 5; k++) {
            int idx = tid + 128 * k;
            if (idx < 576) cp_async16(wdst + idx * 16, wsrc + idx);
        }
    };

    // ---- prologue: stage step 0 ----
    {
        float rv[2];
        stage_w(0, 0);
        cp_commit();
        load_in(0, rv);
        store_in(0, rv);
        cp_wait0();
    }
    __syncthreads();

    for (int s = 0; s < 256; s++) {
        const int cur = s & 1;
        float rv[2];
        if (s < 255) {
            stage_w(1 - cur, s + 1);
            cp_commit();
            load_in(s + 1, rv);
        }

        const float*  s_w   = s_wbuf[cur];
        const float2* s_in2 = s_ibuf[cur];

#pragma unroll
        for (int ic = 0; ic < 2; ic++) {
#pragma unroll
            for (int ky = 0; ky < 3; ky++) {
                // 12 input pairs via 6 x LDS.128 (16B-aligned: x0 even, 42 even)
                const float4* sr4 =
                    (const float4*)(s_in2 + (ic * 3 + ky) * 42 + x0);
                float2 iv[12];
#pragma unroll
                for (int i = 0; i < 6; i++) {
                    float4 q = sr4[i];
                    iv[2 * i]     = make_float2(q.x, q.y);
                    iv[2 * i + 1] = make_float2(q.z, q.w);
                }

                // weights: one LDS.128 per kx covers both oc pairs
                const float4* wrow4 =
                    (const float4*)(s_w + (ic * 9 + ky * 3) * 128) + og;
#pragma unroll
                for (int kx = 0; kx < 3; kx++) {
                    float4 wq = wrow4[kx * 32];      // advance one kk-row = 128 floats
                    float2 w0 = make_float2(wq.x, wq.y);
                    float2 w1 = make_float2(wq.z, wq.w);
#pragma unroll
                    for (int x = 0; x < 10; x++) {
                        fma2(acc[0][x], w0, iv[x + kx]);
                        fma2(acc[1][x], w1, iv[x + kx]);
                    }
                }
            }
        }

        if (s < 255) {
            store_in(1 - cur, rv);
            cp_wait0();
        }
        __syncthreads();
    }

#pragma unroll
    for (int j2 = 0; j2 < 2; j2++) {
        int oc0 = ocg * 128 + og * 4 + j2 * 2;
        float b0 = bias[oc0];
        float b1 = bias[oc0 + 1];
        float* o0 = out + ((long)b * HEAD + oc0) * NPOS + y * FMP + x0;
        float* o1 = o0 + NPOS;
#pragma unroll
        for (int x = 0; x < 10; x++) {
            float v0 = acc[j2][x].x + b0;
            float v1 = acc[j2][x].y + b1;
            o0[x] = v0 > 0.f ? v0 : 0.1f * v0;
            o1[x] = v1 > 0.f ? v1 : 0.1f * v1;
        }
    }
}

// ---------------- 1x1 heads + decode, K-split x2 ----------------
// grid (25, 8), block 128: tid&63 -> position, tid>>6 -> channel half
__global__ void __launch_bounds__(128)
heads_decode_k(const float* __restrict__ cf, const float* __restrict__ rf,
               const float* __restrict__ obj_w, const float* __restrict__ obj_b,
               const float* __restrict__ clsp_w, const float* __restrict__ clsp_b,
               const float* __restrict__ regp_w, const float* __restrict__ regp_b,
               float* __restrict__ out, float* __restrict__ best_s, int* __restrict__ cls_s)
{
    const int b = blockIdx.y;
    const int p = threadIdx.x & 63;
    const int h = threadIdx.x >> 6;
    const int n = blockIdx.x * 64 + p;
    const int ch0 = h * 256;

    const float* cfb = cf + ((long)b * HEAD + ch0) * NPOS + n;
    const float* rfb = rf + ((long)b * HEAD + ch0) * NPOS + n;

    float accC[NCLS];
    float accR[4];
    float accO = 0.f;
#pragma unroll
    for (int c = 0; c < NCLS; c++) accC[c] = 0.f;
#pragma unroll
    for (int k = 0; k < 4; k++) accR[k] = 0.f;

#pragma unroll 4
    for (int ch = 0; ch < 256; ch++) {
        float cv = cfb[(long)ch * NPOS];
        float rv = rfb[(long)ch * NPOS];
        accO = fmaf(rv, __ldg(&obj_w[ch0 + ch]), accO);
#pragma unroll
        for (int k = 0; k < 4; k++)
            accR[k] = fmaf(rv, __ldg(&regp_w[k * HEAD + ch0 + ch]), accR[k]);
#pragma unroll
        for (int c = 0; c < NCLS; c++)
            accC[c] = fmaf(cv, __ldg(&clsp_w[c * HEAD + ch0 + ch]), accC[c]);
    }

    __shared__ float sred[64][25];
    if (h == 1) {
#pragma unroll
        for (int c = 0; c < NCLS; c++) sred[p][c] = accC[c];
#pragma unroll
        for (int k = 0; k < 4; k++) sred[p][NCLS + k] = accR[k];
        sred[p][24] = accO;
    }
    __syncthreads();
    if (h != 0) return;

#pragma unroll
    for (int c = 0; c < NCLS; c++) accC[c] += sred[p][c];
#pragma unroll
    for (int k = 0; k < 4; k++) accR[k] += sred[p][NCLS + k];
    accO += sred[p][24];

    accO += obj_b[0];
#pragma unroll
    for (int k = 0; k < 4; k++) accR[k] += regp_b[k];
#pragma unroll
    for (int c = 0; c < NCLS; c++) accC[c] += clsp_b[c];

    // softmax max / argmax (first-max tie-break, matching jnp.argmax)
    float m = accC[0];
    int am = 0;
#pragma unroll
    for (int c = 1; c < NCLS; c++)
        if (accC[c] > m) { m = accC[c]; am = c; }
    float s = 0.f;
#pragma unroll
    for (int c = 0; c < NCLS; c++) s += expf(accC[c] - m);
    float sig_o = 1.f / (1.f + expf(-accO));
    float best  = sig_o / s;

    float gx = (float)(n % FMP);
    float gy = (float)(n / FMP);
    float cx = 1.f / (1.f + expf(-accR[0])) + gx;
    float cy = 1.f / (1.f + expf(-accR[1])) + gy;
    float ww = expf(accR[2]);
    float hh = expf(accR[3]);

    float bx1 = (cx - ww * 0.5f) * 32.f / 1280.f;
    float by1 = (cy - hh * 0.5f) * 32.f / 1280.f;
    float bx2 = (cx + ww * 0.5f) * 32.f / 1280.f;
    float by2 = (cy + hh * 0.5f) * 32.f / 1280.f;
    bx1 = fminf(fmaxf(bx1, 0.f), 1.f);
    by1 = fminf(fmaxf(by1, 0.f), 1.f);
    bx2 = fminf(fmaxf(bx2, 0.f), 1.f);
    by2 = fminf(fmaxf(by2, 0.f), 1.f);

    const int gi = b * NPOS + n;
    out[gi * 4 + 0] = bx1;
    out[gi * 4 + 1] = by1;
    out[gi * 4 + 2] = bx2;
    out[gi * 4 + 3] = by2;
    out[OFF_BEST + gi] = best;
    out[OFF_CLS  + gi] = (float)am;
    out[OFF_KEEP + gi] = 0.f;
    best_s[gi] = best;
    cls_s[gi]  = am;
}

// ---------------- per-(batch, class) greedy NMS ----------------
__global__ void __launch_bounds__(256)
nms_k(const float* __restrict__ out_boxes,
      float* __restrict__ out_keep,
      const float* __restrict__ best_s, const int* __restrict__ cls_s)
{
    const int b = blockIdx.x / NCLS;
    const int c = blockIdx.x % NCLS;
    const int tid = threadIdx.x;

    __shared__ float sx1[NPOS], sy1[NPOS], sx2[NPOS], sy2[NPOS];
    __shared__ float ssc[NPOS];
    __shared__ int   sidx[NPOS];
    __shared__ unsigned short ord[NPOS];
    __shared__ unsigned char aliveR[NPOS];
    __shared__ int scnt;

    if (tid == 0) scnt = 0;
    __syncthreads();

    for (int n = tid; n < NPOS; n += 256) {
        int gi = b * NPOS + n;
        if (cls_s[gi] == c && best_s[gi] >= CONF_T) {
            int p = atomicAdd(&scnt, 1);
            sidx[p] = n;
            ssc[p]  = best_s[gi];
            const float* bp = out_boxes + (long)gi * 4;
            sx1[p] = bp[0]; sy1[p] = bp[1]; sx2[p] = bp[2]; sy2[p] = bp[3];
        }
    }
    __syncthreads();
    const int cnt = scnt;

    for (int i = tid; i < cnt; i += 256) {
        float si = ssc[i];
        int   ii = sidx[i];
        int rnk = 0;
        for (int j = 0; j < cnt; j++) {
            float sj = ssc[j];
            if (sj > si || (sj == si && sidx[j] < ii)) rnk++;
        }
        ord[rnk] = (unsigned short)i;
        aliveR[rnk] = 1;
    }
    __syncthreads();

    for (int r = 0; r < cnt; r++) {
        __syncthreads();
        if (!aliveR[r]) continue;
        int li = ord[r];
        float bx1 = sx1[li], by1 = sy1[li], bx2 = sx2[li], by2 = sy2[li];
        float ai = (bx2 - bx1) * (by2 - by1);
        for (int rr = r + 1 + tid; rr < cnt; rr += 256) {
            if (!aliveR[rr]) continue;
            int lj = ord[rr];
            float jx1 = sx1[lj], jy1 = sy1[lj], jx2 = sx2[lj], jy2 = sy2[lj];
            float xx1 = fmaxf(bx1, jx1);
            float yy1 = fmaxf(by1, jy1);
            float xx2 = fminf(bx2, jx2);
            float yy2 = fminf(by2, jy2);
            float w2 = fmaxf(1e-28f, xx2 - xx1);
            float h2 = fmaxf(1e-28f, yy2 - yy1);
            float inter = w2 * h2;
            float aj = (jx2 - jx1) * (jy2 - jy1);
            float iou = inter / (ai + aj - inter + 1e-14f);
            if (iou > NMS_T) aliveR[rr] = 0;
        }
    }
    __syncthreads();

    for (int r = tid; r < cnt; r += 256)
        if (aliveR[r])
            out_keep[b * NPOS + sidx[ord[r]]] = 1.f;
}

// ---------------- launch ----------------
extern "C" void kernel_launch(void* const* d_in, const int* in_sizes, int n_in,
                              void* d_out, int out_size)
{
    const float* x      = (const float*)d_in[0];
    const float* cls_w  = (const float*)d_in[1];
    const float* cls_b  = (const float*)d_in[2];
    const float* reg_w  = (const float*)d_in[3];
    const float* reg_b  = (const float*)d_in[4];
    const float* obj_w  = (const float*)d_in[5];
    const float* obj_b  = (const float*)d_in[6];
    const float* clsp_w = (const float*)d_in[7];
    const float* clsp_b = (const float*)d_in[8];
    const float* regp_w = (const float*)d_in[9];
    const float* regp_b = (const float*)d_in[10];
    float* out = (float*)d_out;

    void *pA, *pB, *pC, *pD, *pBest, *pCls, *pWT;
    cudaGetSymbolAddress(&pA, g_bufA);
    cudaGetSymbolAddress(&pB, g_bufB);
    cudaGetSymbolAddress(&pC, g_bufC);
    cudaGetSymbolAddress(&pD, g_bufD);
    cudaGetSymbolAddress(&pBest, g_best);
    cudaGetSymbolAddress(&pCls, g_clsi);
    cudaGetSymbolAddress(&pWT, g_wT);
    float* bufA = (float*)pA;
    float* bufB = (float*)pB;
    float* bufC = (float*)pC;
    float* bufD = (float*)pD;
    float* bestp = (float*)pBest;
    int*   clsp  = (int*)pCls;
    float* wT    = (float*)pWT;

    // streams/events for chain overlap (created once, outside capture)
    static cudaStream_t s2 = 0;
    static cudaEvent_t  evFork = 0, evCls = 0;
    if (!s2) {
        cudaStreamCreateWithFlags(&s2, cudaStreamNonBlocking);
        cudaEventCreateWithFlags(&evFork, cudaEventDisableTiming);
        cudaEventCreateWithFlags(&evCls, cudaEventDisableTiming);
    }

    // one-shot weight transform (deterministic, graph-capturable)
    {
        long total = 6 * WPER;
        int  grid  = (int)((total + 255) / 256);
        wtransform_k<<<grid, 256>>>(cls_w, reg_w, wT);
    }

    dim3 cgrid(FMP, 4, Bs);
    dim3 cblk(128);

    // fork: cls chain on s2, reg chain on default stream
    cudaEventRecord(evFork, 0);
    cudaStreamWaitEvent(s2, evFork, 0);

    // cls branch (s2): x -> bufD -> bufB   (cf = bufB)
    conv3x3_leaky_k<<<cgrid, cblk, 0, s2>>>(x,    wT + 0 * WPER, cls_b,        bufD);
    conv3x3_leaky_k<<<cgrid, cblk, 0, s2>>>(bufD, wT + 1 * WPER, cls_b + HEAD, bufB);
    cudaEventRecord(evCls, s2);

    // reg branch (default): x -> bufA -> bufC -> bufA -> bufC   (rf = bufC)
    conv3x3_leaky_k<<<cgrid, cblk>>>(x,    wT + 2 * WPER, reg_b,            bufA);
    conv3x3_leaky_k<<<cgrid, cblk>>>(bufA, wT + 3 * WPER, reg_b + HEAD,     bufC);
    conv3x3_leaky_k<<<cgrid, cblk>>>(bufC, wT + 4 * WPER, reg_b + 2 * HEAD, bufA);
    conv3x3_leaky_k<<<cgrid, cblk>>>(bufA, wT + 5 * WPER, reg_b + 3 * HEAD, bufC);

    // join: heads needs both chains
    cudaStreamWaitEvent(0, evCls, 0);

    heads_decode_k<<<dim3(25, Bs), 128>>>(bufB, bufC,
                                          obj_w, obj_b, clsp_w, clsp_b,
                                          regp_w, regp_b,
                                          out, bestp, clsp);

    nms_k<<<Bs * NCLS, 256>>>(out, out + OFF_KEEP, bestp, clsp);
}